// round 16
// baseline (speedup 1.0000x reference)
#include <cuda_runtime.h>
#include <cuda_bf16.h>
#include <cuda_fp16.h>
#include <cstdint>
#include <cstddef>

#define DEV __device__ __forceinline__

// ---------------- scratch arena (first ZERO_COUNT floats zeroed) ----------------
__device__ __align__(256) float g_scratch[819200];
__device__ __align__(256) uint32_t g_apre[16777216];  // fp16 enc stage image [att][kst32][m16384][16w]
__device__ __align__(256) uint32_t g_bpre[1048576];   // fp16 fc1-enc weights [att][kst32][n1024][16w]
#define P_E      (g_scratch + 0)
#define O_GI0    32768
#define O_GH0    131072
#define O_GI1    229376
#define O_GH1    327680
#define O_SV2    425984
#define O_FC     491520
#define O_XCAT   524288
#define ZERO_COUNT 622592
#define O_X0     622592
#define O_H0     655360
#define O_SCAT   688128
#define O_ALPHA  753664
#define O_OUT1   786432
#define P_SV2    (g_scratch + O_SV2)
#define P_XCAT   (g_scratch + O_XCAT)
#define P_ALPHA  (g_scratch + O_ALPHA)
#define P_OUT1   (g_scratch + O_OUT1)

DEV float to_tf32(float x) { uint32_t u; asm("cvt.rna.tf32.f32 %0,%1;" : "=r"(u) : "f"(x)); return __uint_as_float(u); }
DEV float tanh_fast(float x) { float y; asm("tanh.approx.f32 %0,%1;" : "=f"(y) : "f"(x)); return y; }
DEV float sigm(float x) { return 1.f / (1.f + expf(-x)); }
DEV void mma8(float c[4], const uint32_t a[4], const uint32_t b[2]) {
    asm volatile("mma.sync.aligned.m16n8k8.row.col.f32.tf32.tf32.f32 "
                 "{%0,%1,%2,%3},{%4,%5,%6,%7},{%8,%9},{%0,%1,%2,%3};"
                 : "+f"(c[0]), "+f"(c[1]), "+f"(c[2]), "+f"(c[3])
                 : "r"(a[0]), "r"(a[1]), "r"(a[2]), "r"(a[3]), "r"(b[0]), "r"(b[1]));
}
DEV void mma16h(float c[4], const uint32_t a[4], uint32_t b0, uint32_t b1) {
    asm volatile("mma.sync.aligned.m16n8k16.row.col.f32.f16.f16.f32 "
                 "{%0,%1,%2,%3},{%4,%5,%6,%7},{%8,%9},{%0,%1,%2,%3};"
                 : "+f"(c[0]), "+f"(c[1]), "+f"(c[2]), "+f"(c[3])
                 : "r"(a[0]), "r"(a[1]), "r"(a[2]), "r"(a[3]), "r"(b0), "r"(b1));
}
DEV uint32_t f16x2(float lo, float hi) {
    uint32_t r; asm("cvt.rn.f16x2.f32 %0,%1,%2;" : "=r"(r) : "f"(hi), "f"(lo)); return r;
}
DEV uint32_t smem_u32(const void* p) {
    uint32_t a; asm("{.reg .u64 t; cvta.to.shared.u64 t, %1; cvt.u32.u64 %0, t;}" : "=r"(a) : "l"(p));
    return a;
}
DEV void cp16(uint32_t dst, const void* src) {
    asm volatile("cp.async.cg.shared.global [%0], [%1], 16;" :: "r"(dst), "l"(src) : "memory");
}
DEV void cp_commit() { asm volatile("cp.async.commit_group;" ::: "memory"); }

// ---------- init: zero accumulators + pack x0 ----------
__global__ void init_kernel(const int* __restrict__ ids, const float* __restrict__ emb) {
    int i = blockIdx.x * 256 + threadIdx.x;
    g_scratch[i] = 0.f;
    if (i < 32768) g_scratch[O_X0 + i] = emb[(size_t)ids[i >> 10] * 1024 + (i & 1023)];
}

// ---------- pre-convert enc/encp to fp16 stage image ----------
__global__ void aconv_kernel(const float* __restrict__ enc, const float* __restrict__ encp) {
    const int u = blockIdx.x * 256 + threadIdx.x;   // 16777216
    const int p = u & 15;
    const int r = (u >> 4) & 16383;
    const int kst = (u >> 18) & 31;
    const int att = u >> 23;
    const float2 v = *(const float2*)((att ? encp : enc) + (size_t)r * 1024 + kst * 32 + p * 2);
    g_apre[u] = f16x2(v.x, v.y);
}

// ---------- pre-convert fc1 enc-part weights to fp16 stage image ----------
__global__ void bconv_kernel(const float* __restrict__ fc1a, const float* __restrict__ fc1p) {
    const int u = blockIdx.x * 256 + threadIdx.x;   // 1048576
    const int p = u & 15;
    const int r = (u >> 4) & 1023;
    const int kst = (u >> 14) & 31;
    const int att = u >> 19;
    const float2 v = *(const float2*)((att ? fc1p : fc1a) + (size_t)r * 3072 + 2048 + kst * 32 + p * 2);
    g_bpre[u] = f16x2(v.x, v.y);
}

// ---------- generic weight-streaming GEMM (3xTF32): out[j*32+b] += sum_k W[j,k]*X[b,k] ----------
__global__ __launch_bounds__(256) void gemm32_kernel(
    const float* __restrict__ Wa, const float* __restrict__ biasa, const float* __restrict__ Xae, int xaoff, int oaoff,
    const float* __restrict__ Wb, const float* __restrict__ biasb, const float* __restrict__ Xbe, int xboff, int oboff,
    int ldw, int K) {
    const float* W = blockIdx.y ? Wb : Wa;
    const float* bias = blockIdx.y ? biasb : biasa;
    const float* X = blockIdx.y ? (Xbe ? Xbe : g_scratch + xboff) : (Xae ? Xae : g_scratch + xaoff);
    float* out = g_scratch + (blockIdx.y ? oboff : oaoff);
    const int m0 = blockIdx.x * 128;
    const int Kc = K / gridDim.z;
    const int k0 = blockIdx.z * Kc;

    __shared__ float Ah[128 * 36], Al[128 * 36], Bh[32 * 36], Bl[32 * 36];
    const int tid = threadIdx.x, lane = tid & 31, wid = tid >> 5;
    const int g = lane >> 2, tg = lane & 3;
    float acc[4][4];
    #pragma unroll
    for (int i = 0; i < 4; i++) { acc[i][0] = acc[i][1] = acc[i][2] = acc[i][3] = 0.f; }

    const int ldrow = tid >> 3, ldc = (tid & 7) * 4;
    for (int t = 0; t < Kc / 32; t++) {
        #pragma unroll
        for (int i = 0; i < 4; i++) {
            float4 v = *(const float4*)(W + (size_t)(m0 + ldrow + i * 32) * ldw + k0 + t * 32 + ldc);
            float4 h, l;
            h.x = to_tf32(v.x); h.y = to_tf32(v.y); h.z = to_tf32(v.z); h.w = to_tf32(v.w);
            l.x = v.x - h.x; l.y = v.y - h.y; l.z = v.z - h.z; l.w = v.w - h.w;
            *(float4*)&Ah[(ldrow + i * 32) * 36 + ldc] = h;
            *(float4*)&Al[(ldrow + i * 32) * 36 + ldc] = l;
        }
        {
            float4 v = *(const float4*)(X + (size_t)ldrow * K + k0 + t * 32 + ldc);
            float4 h, l;
            h.x = to_tf32(v.x); h.y = to_tf32(v.y); h.z = to_tf32(v.z); h.w = to_tf32(v.w);
            l.x = v.x - h.x; l.y = v.y - h.y; l.z = v.z - h.z; l.w = v.w - h.w;
            *(float4*)&Bh[ldrow * 36 + ldc] = h;
            *(float4*)&Bl[ldrow * 36 + ldc] = l;
        }
        __syncthreads();
        #pragma unroll
        for (int kk = 0; kk < 32; kk += 8) {
            uint32_t ah[4], al4[4];
            const int r = (wid * 16 + g) * 36 + kk + tg;
            ah[0] = __float_as_uint(Ah[r]); ah[1] = __float_as_uint(Ah[r + 8 * 36]);
            ah[2] = __float_as_uint(Ah[r + 4]); ah[3] = __float_as_uint(Ah[r + 8 * 36 + 4]);
            al4[0] = __float_as_uint(Al[r]); al4[1] = __float_as_uint(Al[r + 8 * 36]);
            al4[2] = __float_as_uint(Al[r + 4]); al4[3] = __float_as_uint(Al[r + 8 * 36 + 4]);
            #pragma unroll
            for (int ni = 0; ni < 4; ni++) {
                const int rb = (ni * 8 + g) * 36 + kk + tg;
                uint32_t bh[2] = {__float_as_uint(Bh[rb]), __float_as_uint(Bh[rb + 4])};
                uint32_t bl[2] = {__float_as_uint(Bl[rb]), __float_as_uint(Bl[rb + 4])};
                mma8(acc[ni], ah, bh);
                mma8(acc[ni], ah, bl);
                mma8(acc[ni], al4, bh);
            }
        }
        __syncthreads();
    }
    const int j0 = m0 + wid * 16 + g;
    float b0f = 0.f, b8f = 0.f;
    if (bias && blockIdx.z == 0) { b0f = bias[j0]; b8f = bias[j0 + 8]; }
    #pragma unroll
    for (int ni = 0; ni < 4; ni++) {
        const int b = ni * 8 + 2 * tg;
        atomicAdd(&out[j0 * 32 + b], acc[ni][0] + b0f);
        atomicAdd(&out[j0 * 32 + b + 1], acc[ni][1] + b0f);
        atomicAdd(&out[(j0 + 8) * 32 + b], acc[ni][2] + b8f);
        atomicAdd(&out[(j0 + 8) * 32 + b + 1], acc[ni][3] + b8f);
    }
}

// ---------- single-term fp16 GEMM (same contract as gemm32) ----------
__global__ __launch_bounds__(256) void gemm16_kernel(
    const float* __restrict__ Wa, const float* __restrict__ biasa, const float* __restrict__ Xae, int xaoff, int oaoff,
    const float* __restrict__ Wb, const float* __restrict__ biasb, const float* __restrict__ Xbe, int xboff, int oboff,
    int ldw, int K) {
    const float* W = blockIdx.y ? Wb : Wa;
    const float* bias = blockIdx.y ? biasb : biasa;
    const float* X = blockIdx.y ? (Xbe ? Xbe : g_scratch + xboff) : (Xae ? Xae : g_scratch + xaoff);
    float* out = g_scratch + (blockIdx.y ? oboff : oaoff);
    const int m0 = blockIdx.x * 128;
    const int Kc = K / gridDim.z;
    const int k0 = blockIdx.z * Kc;

    __shared__ uint32_t sw[2560], sx[640];   // pitch 20 words, 32 fp16 per row
    const int tid = threadIdx.x, lane = tid & 31, wid = tid >> 5;
    const int g = lane >> 2, tg = lane & 3;
    float acc[4][4];
    #pragma unroll
    for (int i = 0; i < 4; i++) { acc[i][0] = acc[i][1] = acc[i][2] = acc[i][3] = 0.f; }

    const int row2 = tid >> 1, half = tid & 1;
    for (int t = 0; t < Kc / 32; t++) {
        {
            const float* p = W + (size_t)(m0 + row2) * ldw + k0 + t * 32 + half * 16;
            float4 v0 = *(const float4*)p, v1 = *(const float4*)(p + 4);
            float4 v2 = *(const float4*)(p + 8), v3 = *(const float4*)(p + 12);
            *(uint4*)&sw[row2 * 20 + half * 8] =
                make_uint4(f16x2(v0.x, v0.y), f16x2(v0.z, v0.w), f16x2(v1.x, v1.y), f16x2(v1.z, v1.w));
            *(uint4*)&sw[row2 * 20 + half * 8 + 4] =
                make_uint4(f16x2(v2.x, v2.y), f16x2(v2.z, v2.w), f16x2(v3.x, v3.y), f16x2(v3.z, v3.w));
        }
        if (tid < 64) {
            const int xr = tid >> 1, xh = tid & 1;
            const float* p = X + (size_t)xr * K + k0 + t * 32 + xh * 16;
            float4 v0 = *(const float4*)p, v1 = *(const float4*)(p + 4);
            float4 v2 = *(const float4*)(p + 8), v3 = *(const float4*)(p + 12);
            *(uint4*)&sx[xr * 20 + xh * 8] =
                make_uint4(f16x2(v0.x, v0.y), f16x2(v0.z, v0.w), f16x2(v1.x, v1.y), f16x2(v1.z, v1.w));
            *(uint4*)&sx[xr * 20 + xh * 8 + 4] =
                make_uint4(f16x2(v2.x, v2.y), f16x2(v2.z, v2.w), f16x2(v3.x, v3.y), f16x2(v3.z, v3.w));
        }
        __syncthreads();
        #pragma unroll
        for (int kk = 0; kk < 2; kk++) {
            uint32_t af[4];
            const int raw = (wid * 16 + g) * 20 + kk * 8 + tg;
            af[0] = sw[raw]; af[1] = sw[raw + 160]; af[2] = sw[raw + 4]; af[3] = sw[raw + 164];
            #pragma unroll
            for (int ni = 0; ni < 4; ni++) {
                const int rb = (ni * 8 + g) * 20 + kk * 8 + tg;
                mma16h(acc[ni], af, sx[rb], sx[rb + 4]);
            }
        }
        __syncthreads();
    }
    const int j0 = m0 + wid * 16 + g;
    float b0f = 0.f, b8f = 0.f;
    if (bias && blockIdx.z == 0) { b0f = bias[j0]; b8f = bias[j0 + 8]; }
    #pragma unroll
    for (int ni = 0; ni < 4; ni++) {
        const int b = ni * 8 + 2 * tg;
        atomicAdd(&out[j0 * 32 + b], acc[ni][0] + b0f);
        atomicAdd(&out[j0 * 32 + b + 1], acc[ni][1] + b0f);
        atomicAdd(&out[(j0 + 8) * 32 + b], acc[ni][2] + b8f);
        atomicAdd(&out[(j0 + 8) * 32 + b + 1], acc[ni][3] + b8f);
    }
}

// ---------- GRU elementwise combine ----------
__global__ void gru_combine(int gioff, int ghoff, const float* __restrict__ bih,
                            const float* __restrict__ bhh, const float* __restrict__ hprev,
                            int d0off, int s0, int d1off, int s1, float* __restrict__ out_nh) {
    const int t = blockIdx.x * 256 + threadIdx.x;
    const int j = t >> 5, b = t & 31;
    const float* gi = g_scratch + gioff;
    const float* gh = g_scratch + ghoff;
    const float r = sigm(gi[j * 32 + b] + bih[j] + gh[j * 32 + b] + bhh[j]);
    const float z = sigm(gi[(1024 + j) * 32 + b] + bih[1024 + j] + gh[(1024 + j) * 32 + b] + bhh[1024 + j]);
    const float n = tanhf(gi[(2048 + j) * 32 + b] + bih[2048 + j] + r * (gh[(2048 + j) * 32 + b] + bhh[2048 + j]));
    const float h = (1.f - z) * n + z * hprev[b * 1024 + j];
    g_scratch[d0off + b * s0 + j] = h;
    g_scratch[d1off + b * s1 + j] = h;
    out_nh[b * 1024 + j] = h;
}

// ---------- big fused GEMM: fp16 mma, 128x128 tile, pure cp.async 3-stage pipeline ----------
__global__ __launch_bounds__(256, 2) void big_att_f16(
    const float* __restrict__ fc2a, const float* __restrict__ fc2p) {
    extern __shared__ uint32_t sbuf[];
    const int att = blockIdx.z;
    const float* __restrict__ fc2 = att ? fc2p : fc2a;
    const int m0 = blockIdx.y * 128, n0 = blockIdx.x * 128;
    const int tid = threadIdx.x, lane = tid & 31, wid = tid >> 5;
    const int wm = wid >> 2, wn = wid & 3, g = lane >> 2, tg = lane & 3;

    float acc[4][4][4];
    #pragma unroll
    for (int i = 0; i < 4; i++)
        #pragma unroll
        for (int j = 0; j < 4; j++) { acc[i][j][0] = acc[i][j][1] = acc[i][j][2] = acc[i][j][3] = 0.f; }

    const uint32_t sbase = smem_u32(sbuf);
    const int c0row = tid >> 2, c0part = tid & 3;
    const int c1row = 64 + c0row;
    const uint32_t* Aab = g_apre + (size_t)att * 32 * 16384 * 16 + (size_t)m0 * 16;
    const uint32_t* Bab = g_bpre + (size_t)att * 32 * 1024 * 16 + (size_t)n0 * 16;

    #define BA_ISSUE(st) do { \
        const uint32_t base_ = sbase + (uint32_t)(((st) % 3) * 5120) * 4; \
        const uint32_t* As_ = Aab + (size_t)(st) * 16384 * 16; \
        const uint32_t* Bs_ = Bab + (size_t)(st) * 1024 * 16; \
        cp16(base_ + (uint32_t)(c0row * 20 + c0part * 4) * 4, As_ + (size_t)c0row * 16 + c0part * 4); \
        cp16(base_ + (uint32_t)(2560 + c0row * 20 + c0part * 4) * 4, Bs_ + (size_t)c0row * 16 + c0part * 4); \
        cp16(base_ + (uint32_t)(c1row * 20 + c0part * 4) * 4, As_ + (size_t)c1row * 16 + c0part * 4); \
        cp16(base_ + (uint32_t)(2560 + c1row * 20 + c0part * 4) * 4, Bs_ + (size_t)c1row * 16 + c0part * 4); \
        cp_commit(); \
    } while (0)

    BA_ISSUE(0);
    BA_ISSUE(1);
    asm volatile("cp.async.wait_group 1;" ::: "memory");
    __syncthreads();

    for (int st = 0; st < 32; st++) {
        const int cur = (st % 3) * 5120;
        if (st + 2 < 32) BA_ISSUE(st + 2);
        #pragma unroll
        for (int kk = 0; kk < 2; kk++) {
            uint32_t bf[4][2];
            #pragma unroll
            for (int ni = 0; ni < 4; ni++) {
                const int rbw = cur + 2560 + (wn * 32 + ni * 8 + g) * 20 + kk * 8 + tg;
                bf[ni][0] = sbuf[rbw];
                bf[ni][1] = sbuf[rbw + 4];
            }
            #pragma unroll
            for (int mi = 0; mi < 4; mi++) {
                uint32_t af[4];
                const int raw = cur + (wm * 64 + mi * 16 + g) * 20 + kk * 8 + tg;
                af[0] = sbuf[raw];
                af[1] = sbuf[raw + 160];
                af[2] = sbuf[raw + 4];
                af[3] = sbuf[raw + 164];
                mma16h(acc[mi][0], af, bf[0][0], bf[0][1]);
                mma16h(acc[mi][1], af, bf[1][0], bf[1][1]);
                mma16h(acc[mi][2], af, bf[2][0], bf[2][1]);
                mma16h(acc[mi][3], af, bf[3][0], bf[3][1]);
            }
        }
        if (st + 2 < 32) asm volatile("cp.async.wait_group 1;" ::: "memory");
        else asm volatile("cp.async.wait_group 0;" ::: "memory");
        __syncthreads();
    }
    #undef BA_ISSUE

    float* svs = (float*)sbuf;          // [32][132]
    float* fc2s = svs + 32 * 132;       // [128]
    for (int idx = tid; idx < 32 * 128; idx += 256)
        svs[(idx >> 7) * 132 + (idx & 127)] = P_SV2[att * 32768 + (n0 + (idx & 127)) * 32 + (idx >> 7)];
    if (tid < 128) fc2s[tid] = fc2[n0 + tid];
    __syncthreads();

    float part[8] = {0, 0, 0, 0, 0, 0, 0, 0};
    #pragma unroll
    for (int mi = 0; mi < 4; mi++) {
        const int bA = (mi & 1) * 16 + g, bB = bA + 8;
        #pragma unroll
        for (int ni = 0; ni < 4; ni++) {
            const int j = wn * 32 + ni * 8 + 2 * tg;
            const float f0 = fc2s[j], f1 = fc2s[j + 1];
            part[mi * 2] += f0 * tanh_fast(acc[mi][ni][0] + svs[bA * 132 + j])
                          + f1 * tanh_fast(acc[mi][ni][1] + svs[bA * 132 + j + 1]);
            part[mi * 2 + 1] += f0 * tanh_fast(acc[mi][ni][2] + svs[bB * 132 + j])
                              + f1 * tanh_fast(acc[mi][ni][3] + svs[bB * 132 + j + 1]);
        }
    }
    #pragma unroll
    for (int o = 1; o <= 2; o <<= 1)
        #pragma unroll
        for (int r = 0; r < 8; r++) part[r] += __shfl_xor_sync(~0u, part[r], o);
    if (tg == 0) {
        #pragma unroll
        for (int mi = 0; mi < 4; mi++) {
            atomicAdd(&P_E[att * 16384 + m0 + wm * 64 + mi * 16 + g], part[mi * 2]);
            atomicAdd(&P_E[att * 16384 + m0 + wm * 64 + mi * 16 + g + 8], part[mi * 2 + 1]);
        }
    }
}

// ---------- softmax over s ----------
__global__ void softmax_kernel() {
    const int b = blockIdx.x, att = blockIdx.y, s = threadIdx.x;
    __shared__ float red[512];
    const float v = P_E[att * 16384 + s * 32 + b];
    red[s] = v; __syncthreads();
    for (int o = 256; o > 0; o >>= 1) { if (s < o) red[s] = fmaxf(red[s], red[s + o]); __syncthreads(); }
    const float m = red[0]; __syncthreads();
    const float ex = expf(v - m);
    red[s] = ex; __syncthreads();
    for (int o = 256; o > 0; o >>= 1) { if (s < o) red[s] += red[s + o]; __syncthreads(); }
    P_ALPHA[att * 16384 + b * 512 + s] = ex / red[0];
}

// ---------- context (s-split) -> xcat cols 1024.. ----------
__global__ void ctx_kernel(const float* __restrict__ enc, const float* __restrict__ encp) {
    const int b = blockIdx.x, att = blockIdx.y, s0 = blockIdx.z * 64, tid = threadIdx.x;
    const float* E = att ? encp : enc;
    __shared__ float al[64];
    if (tid < 64) al[tid] = P_ALPHA[att * 16384 + b * 512 + s0 + tid];
    __syncthreads();
    float a0 = 0, a1 = 0, a2 = 0, a3 = 0;
    #pragma unroll 4
    for (int i = 0; i < 64; i++) {
        const float a = al[i];
        const float* row = E + ((size_t)(s0 + i) * 32 + b) * 1024 + tid;
        a0 += a * row[0]; a1 += a * row[256]; a2 += a * row[512]; a3 += a * row[768];
    }
    float* c = P_XCAT + b * 3072 + 1024 + att * 1024 + tid;
    atomicAdd(c, a0); atomicAdd(c + 256, a1); atomicAdd(c + 512, a2); atomicAdd(c + 768, a3);
}

// ---------- relu + transpose ----------
__global__ void relu_tr_kernel() {
    const int t = blockIdx.x * 256 + threadIdx.x;
    P_OUT1[(t & 31) * 1024 + (t >> 5)] = fmaxf(g_scratch[O_FC + t], 0.f);
}

// ---------- logits: single-term fp16 mma, M=32000 N=32 K=1024 ----------
__global__ __launch_bounds__(256) void logits_f16(const float* __restrict__ fcw,
                                                  const float* __restrict__ fcb,
                                                  float* __restrict__ out) {
    const int m0 = blockIdx.x * 128;
    __shared__ uint32_t sw[2560], sx[640];
    const int tid = threadIdx.x, lane = tid & 31, wid = tid >> 5;
    const int g = lane >> 2, tg = lane & 3;
    float acc[4][4];
    #pragma unroll
    for (int i = 0; i < 4; i++) { acc[i][0] = acc[i][1] = acc[i][2] = acc[i][3] = 0.f; }

    const int row2 = tid >> 1, half = tid & 1;
    for (int t = 0; t < 32; t++) {
        {
            const float* p = fcw + (size_t)(m0 + row2) * 1024 + t * 32 + half * 16;
            float4 v0 = *(const float4*)p, v1 = *(const float4*)(p + 4);
            float4 v2 = *(const float4*)(p + 8), v3 = *(const float4*)(p + 12);
            *(uint4*)&sw[row2 * 20 + half * 8] =
                make_uint4(f16x2(v0.x, v0.y), f16x2(v0.z, v0.w), f16x2(v1.x, v1.y), f16x2(v1.z, v1.w));
            *(uint4*)&sw[row2 * 20 + half * 8 + 4] =
                make_uint4(f16x2(v2.x, v2.y), f16x2(v2.z, v2.w), f16x2(v3.x, v3.y), f16x2(v3.z, v3.w));
        }
        if (tid < 64) {
            const int xr = tid >> 1, xh = tid & 1;
            const float* p = P_OUT1 + (size_t)xr * 1024 + t * 32 + xh * 16;
            float4 v0 = *(const float4*)p, v1 = *(const float4*)(p + 4);
            float4 v2 = *(const float4*)(p + 8), v3 = *(const float4*)(p + 12);
            *(uint4*)&sx[xr * 20 + xh * 8] =
                make_uint4(f16x2(v0.x, v0.y), f16x2(v0.z, v0.w), f16x2(v1.x, v1.y), f16x2(v1.z, v1.w));
            *(uint4*)&sx[xr * 20 + xh * 8 + 4] =
                make_uint4(f16x2(v2.x, v2.y), f16x2(v2.z, v2.w), f16x2(v3.x, v3.y), f16x2(v3.z, v3.w));
        }
        __syncthreads();
        #pragma unroll
        for (int kk = 0; kk < 2; kk++) {
            uint32_t af[4];
            const int raw = (wid * 16 + g) * 20 + kk * 8 + tg;
            af[0] = sw[raw]; af[1] = sw[raw + 160]; af[2] = sw[raw + 4]; af[3] = sw[raw + 164];
            #pragma unroll
            for (int ni = 0; ni < 4; ni++) {
                const int rb = (ni * 8 + g) * 20 + kk * 8 + tg;
                mma16h(acc[ni], af, sx[rb], sx[rb + 4]);
            }
        }
        __syncthreads();
    }
    const int j0 = m0 + wid * 16 + g;
    const float b0f = fcb[j0], b8f = fcb[j0 + 8];
    #pragma unroll
    for (int ni = 0; ni < 4; ni++) {
        const int b = ni * 8 + 2 * tg;
        out[(size_t)b * 32000 + j0] = acc[ni][0] + b0f;
        out[(size_t)(b + 1) * 32000 + j0] = acc[ni][1] + b0f;
        out[(size_t)b * 32000 + j0 + 8] = acc[ni][2] + b8f;
        out[(size_t)(b + 1) * 32000 + j0 + 8] = acc[ni][3] + b8f;
    }
}

extern "C" void kernel_launch(void* const* d_in, const int* in_sizes, int n_in,
                              void* d_out, int out_size) {
    (void)in_sizes; (void)n_in; (void)out_size;
    const int* ids = (const int*)d_in[0];
    const float* hidden = (const float*)d_in[1];
    const float* enc = (const float*)d_in[2];
    const float* encp = (const float*)d_in[3];
    const float* emb = (const float*)d_in[4];
    const float* Wih0 = (const float*)d_in[5];
    const float* Whh0 = (const float*)d_in[6];
    const float* bih0 = (const float*)d_in[7];
    const float* bhh0 = (const float*)d_in[8];
    const float* Wih1 = (const float*)d_in[9];
    const float* Whh1 = (const float*)d_in[10];
    const float* bih1 = (const float*)d_in[11];
    const float* bhh1 = (const float*)d_in[12];
    const float* afc1w = (const float*)d_in[13];
    const float* afc1b = (const float*)d_in[14];
    const float* afc2w = (const float*)d_in[15];
    const float* pfc1w = (const float*)d_in[17];
    const float* pfc1b = (const float*)d_in[18];
    const float* pfc2w = (const float*)d_in[19];
    const float* nfcw = (const float*)d_in[21];
    const float* nfcb = (const float*)d_in[22];
    const float* fcw = (const float*)d_in[23];
    const float* fcb = (const float*)d_in[24];
    float* out = (float*)d_out;
    float* out_nh = out + 1024000;

    cudaFuncSetAttribute(big_att_f16, cudaFuncAttributeMaxDynamicSharedMemorySize, 61440);

    init_kernel<<<ZERO_COUNT / 256, 256>>>(ids, emb);
    aconv_kernel<<<65536, 256>>>(enc, encp);
    bconv_kernel<<<4096, 256>>>(afc1w, pfc1w);
    gemm16_kernel<<<dim3(24, 2, 8), 256>>>(Wih0, nullptr, nullptr, O_X0, O_GI0,
                                           Whh0, nullptr, hidden, 0, O_GH0, 1024, 1024);
    gru_combine<<<128, 256>>>(O_GI0, O_GH0, bih0, bhh0, hidden, O_H0, 1024, O_SCAT, 2048, out_nh);
    gemm16_kernel<<<dim3(24, 2, 8), 256>>>(Wih1, nullptr, nullptr, O_H0, O_GI1,
                                           Whh1, nullptr, hidden + 32768, 0, O_GH1, 1024, 1024);
    gru_combine<<<128, 256>>>(O_GI1, O_GH1, bih1, bhh1, hidden + 32768,
                              O_XCAT, 3072, O_SCAT + 1024, 2048, out_nh + 32768);
    gemm32_kernel<<<dim3(8, 2, 8), 256>>>(afc1w, afc1b, nullptr, O_SCAT, O_SV2,
                                          pfc1w, pfc1b, nullptr, O_SCAT, O_SV2 + 32768, 3072, 2048);
    big_att_f16<<<dim3(8, 128, 2), 256, 61440>>>(afc2w, pfc2w);
    softmax_kernel<<<dim3(32, 2), 512>>>();
    ctx_kernel<<<dim3(32, 2, 8), 256>>>(enc, encp);
    gemm32_kernel<<<dim3(8, 1, 8), 256>>>(nfcw, nfcb, nullptr, O_XCAT, O_FC,
                                          nfcw, nfcb, nullptr, O_XCAT, O_FC, 3072, 3072);
    relu_tr_kernel<<<128, 256>>>();
    logits_f16<<<250, 256>>>(fcw, fcb, out);
}

// round 17
// speedup vs baseline: 1.0314x; 1.0314x over previous
#include <cuda_runtime.h>
#include <cuda_fp16.h>
#include <cstdint>
#include <cstddef>

#define DEV __device__ __forceinline__

// ---------------- scratch arena (first ZERO_COUNT floats zeroed) ----------------
__device__ __align__(256) float g_scratch[819200];
#define P_E      (g_scratch + 0)
#define O_GI0    32768
#define O_GH0    131072
#define O_GI1    229376
#define O_GH1    327680
#define O_SV2    425984
#define O_FC     491520
#define O_XCAT   524288
#define ZERO_COUNT 622592
#define O_X0     622592
#define O_H0     655360
#define O_SCAT   688128
#define O_ALPHA  753664
#define O_OUT1   786432
#define P_SV2    (g_scratch + O_SV2)
#define P_XCAT   (g_scratch + O_XCAT)
#define P_ALPHA  (g_scratch + O_ALPHA)
#define P_OUT1   (g_scratch + O_OUT1)

DEV float tanh_fast(float x) { float y; asm("tanh.approx.f32 %0,%1;" : "=f"(y) : "f"(x)); return y; }
DEV float sigm(float x) { return 1.f / (1.f + expf(-x)); }
DEV void mma16h(float c[4], const uint32_t a[4], uint32_t b0, uint32_t b1) {
    asm volatile("mma.sync.aligned.m16n8k16.row.col.f32.f16.f16.f32 "
                 "{%0,%1,%2,%3},{%4,%5,%6,%7},{%8,%9},{%0,%1,%2,%3};"
                 : "+f"(c[0]), "+f"(c[1]), "+f"(c[2]), "+f"(c[3])
                 : "r"(a[0]), "r"(a[1]), "r"(a[2]), "r"(a[3]), "r"(b0), "r"(b1));
}
DEV uint32_t f16x2(float lo, float hi) {
    uint32_t r; asm("cvt.rn.f16x2.f32 %0,%1,%2;" : "=r"(r) : "f"(hi), "f"(lo)); return r;
}

// ---------- init: zero accumulators + pack x0 ----------
__global__ void init_kernel(const int* __restrict__ ids, const float* __restrict__ emb) {
    int i = blockIdx.x * 256 + threadIdx.x;
    g_scratch[i] = 0.f;
    if (i < 32768) g_scratch[O_X0 + i] = emb[(size_t)ids[i >> 10] * 1024 + (i & 1023)];
}

// ---------- single-term fp16 GEMM: out[j*32+b] += sum_k W[j,k]*X[b,k] ----------
// grid (M/128, nsets, ksplit). Scratch operands via offsets; external X via pointer.
__global__ __launch_bounds__(256) void gemm16_kernel(
    const float* __restrict__ Wa, const float* __restrict__ biasa, const float* __restrict__ Xae, int xaoff, int oaoff,
    const float* __restrict__ Wb, const float* __restrict__ biasb, const float* __restrict__ Xbe, int xboff, int oboff,
    int ldw, int K) {
    const float* W = blockIdx.y ? Wb : Wa;
    const float* bias = blockIdx.y ? biasb : biasa;
    const float* X = blockIdx.y ? (Xbe ? Xbe : g_scratch + xboff) : (Xae ? Xae : g_scratch + xaoff);
    float* out = g_scratch + (blockIdx.y ? oboff : oaoff);
    const int m0 = blockIdx.x * 128;
    const int Kc = K / gridDim.z;
    const int k0 = blockIdx.z * Kc;

    __shared__ uint32_t sw[2560], sx[640];   // pitch 20 words, 32 fp16 per row
    const int tid = threadIdx.x, lane = tid & 31, wid = tid >> 5;
    const int g = lane >> 2, tg = lane & 3;
    float acc[4][4];
    #pragma unroll
    for (int i = 0; i < 4; i++) { acc[i][0] = acc[i][1] = acc[i][2] = acc[i][3] = 0.f; }

    const int row2 = tid >> 1, half = tid & 1;
    for (int t = 0; t < Kc / 32; t++) {
        {
            const float* p = W + (size_t)(m0 + row2) * ldw + k0 + t * 32 + half * 16;
            float4 v0 = *(const float4*)p, v1 = *(const float4*)(p + 4);
            float4 v2 = *(const float4*)(p + 8), v3 = *(const float4*)(p + 12);
            *(uint4*)&sw[row2 * 20 + half * 8] =
                make_uint4(f16x2(v0.x, v0.y), f16x2(v0.z, v0.w), f16x2(v1.x, v1.y), f16x2(v1.z, v1.w));
            *(uint4*)&sw[row2 * 20 + half * 8 + 4] =
                make_uint4(f16x2(v2.x, v2.y), f16x2(v2.z, v2.w), f16x2(v3.x, v3.y), f16x2(v3.z, v3.w));
        }
        if (tid < 64) {
            const int xr = tid >> 1, xh = tid & 1;
            const float* p = X + (size_t)xr * K + k0 + t * 32 + xh * 16;
            float4 v0 = *(const float4*)p, v1 = *(const float4*)(p + 4);
            float4 v2 = *(const float4*)(p + 8), v3 = *(const float4*)(p + 12);
            *(uint4*)&sx[xr * 20 + xh * 8] =
                make_uint4(f16x2(v0.x, v0.y), f16x2(v0.z, v0.w), f16x2(v1.x, v1.y), f16x2(v1.z, v1.w));
            *(uint4*)&sx[xr * 20 + xh * 8 + 4] =
                make_uint4(f16x2(v2.x, v2.y), f16x2(v2.z, v2.w), f16x2(v3.x, v3.y), f16x2(v3.z, v3.w));
        }
        __syncthreads();
        #pragma unroll
        for (int kk = 0; kk < 2; kk++) {
            uint32_t af[4];
            const int raw = (wid * 16 + g) * 20 + kk * 8 + tg;
            af[0] = sw[raw]; af[1] = sw[raw + 160]; af[2] = sw[raw + 4]; af[3] = sw[raw + 164];
            #pragma unroll
            for (int ni = 0; ni < 4; ni++) {
                const int rb = (ni * 8 + g) * 20 + kk * 8 + tg;
                mma16h(acc[ni], af, sx[rb], sx[rb + 4]);
            }
        }
        __syncthreads();
    }
    const int j0 = m0 + wid * 16 + g;
    float b0f = 0.f, b8f = 0.f;
    if (bias && blockIdx.z == 0) { b0f = bias[j0]; b8f = bias[j0 + 8]; }
    #pragma unroll
    for (int ni = 0; ni < 4; ni++) {
        const int b = ni * 8 + 2 * tg;
        atomicAdd(&out[j0 * 32 + b], acc[ni][0] + b0f);
        atomicAdd(&out[j0 * 32 + b + 1], acc[ni][1] + b0f);
        atomicAdd(&out[(j0 + 8) * 32 + b], acc[ni][2] + b8f);
        atomicAdd(&out[(j0 + 8) * 32 + b + 1], acc[ni][3] + b8f);
    }
}

// ---------- GRU elementwise combine ----------
__global__ void gru_combine(int gioff, int ghoff, const float* __restrict__ bih,
                            const float* __restrict__ bhh, const float* __restrict__ hprev,
                            int d0off, int s0, int d1off, int s1, float* __restrict__ out_nh) {
    const int t = blockIdx.x * 256 + threadIdx.x;
    const int j = t >> 5, b = t & 31;
    const float* gi = g_scratch + gioff;
    const float* gh = g_scratch + ghoff;
    const float r = sigm(gi[j * 32 + b] + bih[j] + gh[j * 32 + b] + bhh[j]);
    const float z = sigm(gi[(1024 + j) * 32 + b] + bih[1024 + j] + gh[(1024 + j) * 32 + b] + bhh[1024 + j]);
    const float n = tanhf(gi[(2048 + j) * 32 + b] + bih[2048 + j] + r * (gh[(2048 + j) * 32 + b] + bhh[2048 + j]));
    const float h = (1.f - z) * n + z * hprev[b * 1024 + j];
    g_scratch[d0off + b * s0 + j] = h;
    g_scratch[d1off + b * s1 + j] = h;
    out_nh[b * 1024 + j] = h;
}

// ---------- big fused GEMM: single-term fp16 mma, double-buffered, 1 sync/stage (R13) ----------
__global__ __launch_bounds__(256) void big_att_f16(
    const float* __restrict__ enc, const float* __restrict__ encp,
    const float* __restrict__ fc1a, const float* __restrict__ fc1p,
    const float* __restrict__ fc2a, const float* __restrict__ fc2p) {
    __shared__ uint32_t sbuf[10240];
    const int att = blockIdx.z;
    const float* __restrict__ A = att ? encp : enc;
    const float* __restrict__ W = att ? fc1p : fc1a;
    const float* __restrict__ fc2 = att ? fc2p : fc2a;
    const int m0 = blockIdx.y * 128, n0 = blockIdx.x * 128;
    const int tid = threadIdx.x, lane = tid & 31, wid = tid >> 5;
    const int wm = wid >> 2, wn = wid & 3, g = lane >> 2, tg = lane & 3;

    float acc[4][4][4];
    #pragma unroll
    for (int i = 0; i < 4; i++)
        #pragma unroll
        for (int j = 0; j < 4; j++) { acc[i][j][0] = acc[i][j][1] = acc[i][j][2] = acc[i][j][3] = 0.f; }

    const int ldrow = tid >> 3, ldc = (tid & 7) * 4;
    const float* Ap = A + (size_t)(m0 + ldrow) * 1024 + ldc;
    const float* Wp = W + (size_t)(n0 + ldrow) * 3072 + 2048 + ldc;
    const int sA0 = ldrow * 20 + (tid & 7) * 2;
    const int sB0 = 2560 + sA0;

    float4 ra[4], rb[4];
    #pragma unroll
    for (int i = 0; i < 4; i++) {
        ra[i] = *(const float4*)(Ap + (size_t)i * 32 * 1024);
        rb[i] = *(const float4*)(Wp + (size_t)i * 32 * 3072);
    }
    #pragma unroll
    for (int i = 0; i < 4; i++) {
        sbuf[sA0 + i * 640] = f16x2(ra[i].x, ra[i].y);
        sbuf[sA0 + i * 640 + 1] = f16x2(ra[i].z, ra[i].w);
        sbuf[sB0 + i * 640] = f16x2(rb[i].x, rb[i].y);
        sbuf[sB0 + i * 640 + 1] = f16x2(rb[i].z, rb[i].w);
    }
    #pragma unroll
    for (int i = 0; i < 4; i++) {
        ra[i] = *(const float4*)(Ap + (size_t)i * 32 * 1024 + 32);
        rb[i] = *(const float4*)(Wp + (size_t)i * 32 * 3072 + 32);
    }
    __syncthreads();

    for (int st = 0; st < 32; st++) {
        const int cur = (st & 1) * 5120;
        const int nxt = ((st + 1) & 1) * 5120;
        if (st < 31) {
            #pragma unroll
            for (int i = 0; i < 4; i++) {
                sbuf[nxt + sA0 + i * 640] = f16x2(ra[i].x, ra[i].y);
                sbuf[nxt + sA0 + i * 640 + 1] = f16x2(ra[i].z, ra[i].w);
                sbuf[nxt + sB0 + i * 640] = f16x2(rb[i].x, rb[i].y);
                sbuf[nxt + sB0 + i * 640 + 1] = f16x2(rb[i].z, rb[i].w);
            }
        }
        if (st < 30) {
            const int o = (st + 2) * 32;
            #pragma unroll
            for (int i = 0; i < 4; i++) {
                ra[i] = *(const float4*)(Ap + (size_t)i * 32 * 1024 + o);
                rb[i] = *(const float4*)(Wp + (size_t)i * 32 * 3072 + o);
            }
        }
        #pragma unroll
        for (int kk = 0; kk < 2; kk++) {
            uint32_t bf[4][2];
            #pragma unroll
            for (int ni = 0; ni < 4; ni++) {
                const int rbw = cur + 2560 + (wn * 32 + ni * 8 + g) * 20 + kk * 8 + tg;
                bf[ni][0] = sbuf[rbw];
                bf[ni][1] = sbuf[rbw + 4];
            }
            #pragma unroll
            for (int mi = 0; mi < 4; mi++) {
                uint32_t af[4];
                const int raw = cur + (wm * 64 + mi * 16 + g) * 20 + kk * 8 + tg;
                af[0] = sbuf[raw];
                af[1] = sbuf[raw + 160];
                af[2] = sbuf[raw + 4];
                af[3] = sbuf[raw + 164];
                mma16h(acc[mi][0], af, bf[0][0], bf[0][1]);
                mma16h(acc[mi][1], af, bf[1][0], bf[1][1]);
                mma16h(acc[mi][2], af, bf[2][0], bf[2][1]);
                mma16h(acc[mi][3], af, bf[3][0], bf[3][1]);
            }
        }
        __syncthreads();
    }

    // epilogue: e[m] += sum_j fc2[j]*tanh(C + sv[b][j]),  b = m & 31
    float* svs = (float*)sbuf;          // [32][132]
    float* fc2s = svs + 32 * 132;       // [128]
    for (int idx = tid; idx < 32 * 128; idx += 256)
        svs[(idx >> 7) * 132 + (idx & 127)] = P_SV2[att * 32768 + (n0 + (idx & 127)) * 32 + (idx >> 7)];
    if (tid < 128) fc2s[tid] = fc2[n0 + tid];
    __syncthreads();

    float part[8] = {0, 0, 0, 0, 0, 0, 0, 0};
    #pragma unroll
    for (int mi = 0; mi < 4; mi++) {
        const int bA = (mi & 1) * 16 + g, bB = bA + 8;
        #pragma unroll
        for (int ni = 0; ni < 4; ni++) {
            const int j = wn * 32 + ni * 8 + 2 * tg;
            const float f0 = fc2s[j], f1 = fc2s[j + 1];
            part[mi * 2] += f0 * tanh_fast(acc[mi][ni][0] + svs[bA * 132 + j])
                          + f1 * tanh_fast(acc[mi][ni][1] + svs[bA * 132 + j + 1]);
            part[mi * 2 + 1] += f0 * tanh_fast(acc[mi][ni][2] + svs[bB * 132 + j])
                              + f1 * tanh_fast(acc[mi][ni][3] + svs[bB * 132 + j + 1]);
        }
    }
    #pragma unroll
    for (int o = 1; o <= 2; o <<= 1)
        #pragma unroll
        for (int r = 0; r < 8; r++) part[r] += __shfl_xor_sync(~0u, part[r], o);
    if (tg == 0) {
        #pragma unroll
        for (int mi = 0; mi < 4; mi++) {
            atomicAdd(&P_E[att * 16384 + m0 + wm * 64 + mi * 16 + g], part[mi * 2]);
            atomicAdd(&P_E[att * 16384 + m0 + wm * 64 + mi * 16 + g + 8], part[mi * 2 + 1]);
        }
    }
}

// ---------- softmax over s ----------
__global__ void softmax_kernel() {
    const int b = blockIdx.x, att = blockIdx.y, s = threadIdx.x;
    __shared__ float red[512];
    const float v = P_E[att * 16384 + s * 32 + b];
    red[s] = v; __syncthreads();
    for (int o = 256; o > 0; o >>= 1) { if (s < o) red[s] = fmaxf(red[s], red[s + o]); __syncthreads(); }
    const float m = red[0]; __syncthreads();
    const float ex = expf(v - m);
    red[s] = ex; __syncthreads();
    for (int o = 256; o > 0; o >>= 1) { if (s < o) red[s] += red[s + o]; __syncthreads(); }
    P_ALPHA[att * 16384 + b * 512 + s] = ex / red[0];
}

// ---------- context (s-split) -> xcat cols 1024.. ----------
__global__ void ctx_kernel(const float* __restrict__ enc, const float* __restrict__ encp) {
    const int b = blockIdx.x, att = blockIdx.y, s0 = blockIdx.z * 64, tid = threadIdx.x;
    const float* E = att ? encp : enc;
    __shared__ float al[64];
    if (tid < 64) al[tid] = P_ALPHA[att * 16384 + b * 512 + s0 + tid];
    __syncthreads();
    float a0 = 0, a1 = 0, a2 = 0, a3 = 0;
    #pragma unroll 4
    for (int i = 0; i < 64; i++) {
        const float a = al[i];
        const float* row = E + ((size_t)(s0 + i) * 32 + b) * 1024 + tid;
        a0 += a * row[0]; a1 += a * row[256]; a2 += a * row[512]; a3 += a * row[768];
    }
    float* c = P_XCAT + b * 3072 + 1024 + att * 1024 + tid;
    atomicAdd(c, a0); atomicAdd(c + 256, a1); atomicAdd(c + 512, a2); atomicAdd(c + 768, a3);
}

// ---------- relu + transpose ----------
__global__ void relu_tr_kernel() {
    const int t = blockIdx.x * 256 + threadIdx.x;
    P_OUT1[(t & 31) * 1024 + (t >> 5)] = fmaxf(g_scratch[O_FC + t], 0.f);
}

// ---------- logits: single-term fp16 mma, M=32000 N=32 K=1024 ----------
__global__ __launch_bounds__(256) void logits_f16(const float* __restrict__ fcw,
                                                  const float* __restrict__ fcb,
                                                  float* __restrict__ out) {
    const int m0 = blockIdx.x * 128;
    __shared__ uint32_t sw[2560], sx[640];
    const int tid = threadIdx.x, lane = tid & 31, wid = tid >> 5;
    const int g = lane >> 2, tg = lane & 3;
    float acc[4][4];
    #pragma unroll
    for (int i = 0; i < 4; i++) { acc[i][0] = acc[i][1] = acc[i][2] = acc[i][3] = 0.f; }

    const int row2 = tid >> 1, half = tid & 1;
    for (int t = 0; t < 32; t++) {
        {
            const float* p = fcw + (size_t)(m0 + row2) * 1024 + t * 32 + half * 16;
            float4 v0 = *(const float4*)p, v1 = *(const float4*)(p + 4);
            float4 v2 = *(const float4*)(p + 8), v3 = *(const float4*)(p + 12);
            *(uint4*)&sw[row2 * 20 + half * 8] =
                make_uint4(f16x2(v0.x, v0.y), f16x2(v0.z, v0.w), f16x2(v1.x, v1.y), f16x2(v1.z, v1.w));
            *(uint4*)&sw[row2 * 20 + half * 8 + 4] =
                make_uint4(f16x2(v2.x, v2.y), f16x2(v2.z, v2.w), f16x2(v3.x, v3.y), f16x2(v3.z, v3.w));
        }
        if (tid < 64) {
            const int xr = tid >> 1, xh = tid & 1;
            const float* p = P_OUT1 + (size_t)xr * 1024 + t * 32 + xh * 16;
            float4 v0 = *(const float4*)p, v1 = *(const float4*)(p + 4);
            float4 v2 = *(const float4*)(p + 8), v3 = *(const float4*)(p + 12);
            *(uint4*)&sx[xr * 20 + xh * 8] =
                make_uint4(f16x2(v0.x, v0.y), f16x2(v0.z, v0.w), f16x2(v1.x, v1.y), f16x2(v1.z, v1.w));
            *(uint4*)&sx[xr * 20 + xh * 8 + 4] =
                make_uint4(f16x2(v2.x, v2.y), f16x2(v2.z, v2.w), f16x2(v3.x, v3.y), f16x2(v3.z, v3.w));
        }
        __syncthreads();
        #pragma unroll
        for (int kk = 0; kk < 2; kk++) {
            uint32_t af[4];
            const int raw = (wid * 16 + g) * 20 + kk * 8 + tg;
            af[0] = sw[raw]; af[1] = sw[raw + 160]; af[2] = sw[raw + 4]; af[3] = sw[raw + 164];
            #pragma unroll
            for (int ni = 0; ni < 4; ni++) {
                const int rb = (ni * 8 + g) * 20 + kk * 8 + tg;
                mma16h(acc[ni], af, sx[rb], sx[rb + 4]);
            }
        }
        __syncthreads();
    }
    const int j0 = m0 + wid * 16 + g;
    const float b0f = fcb[j0], b8f = fcb[j0 + 8];
    #pragma unroll
    for (int ni = 0; ni < 4; ni++) {
        const int b = ni * 8 + 2 * tg;
        out[(size_t)b * 32000 + j0] = acc[ni][0] + b0f;
        out[(size_t)(b + 1) * 32000 + j0] = acc[ni][1] + b0f;
        out[(size_t)b * 32000 + j0 + 8] = acc[ni][2] + b8f;
        out[(size_t)(b + 1) * 32000 + j0 + 8] = acc[ni][3] + b8f;
    }
}

extern "C" void kernel_launch(void* const* d_in, const int* in_sizes, int n_in,
                              void* d_out, int out_size) {
    (void)in_sizes; (void)n_in; (void)out_size;
    const int* ids = (const int*)d_in[0];
    const float* hidden = (const float*)d_in[1];
    const float* enc = (const float*)d_in[2];
    const float* encp = (const float*)d_in[3];
    const float* emb = (const float*)d_in[4];
    const float* Wih0 = (const float*)d_in[5];
    const float* Whh0 = (const float*)d_in[6];
    const float* bih0 = (const float*)d_in[7];
    const float* bhh0 = (const float*)d_in[8];
    const float* Wih1 = (const float*)d_in[9];
    const float* Whh1 = (const float*)d_in[10];
    const float* bih1 = (const float*)d_in[11];
    const float* bhh1 = (const float*)d_in[12];
    const float* afc1w = (const float*)d_in[13];
    const float* afc1b = (const float*)d_in[14];
    const float* afc2w = (const float*)d_in[15];
    const float* pfc1w = (const float*)d_in[17];
    const float* pfc1b = (const float*)d_in[18];
    const float* pfc2w = (const float*)d_in[19];
    const float* nfcw = (const float*)d_in[21];
    const float* nfcb = (const float*)d_in[22];
    const float* fcw = (const float*)d_in[23];
    const float* fcb = (const float*)d_in[24];
    float* out = (float*)d_out;
    float* out_nh = out + 1024000;

    init_kernel<<<ZERO_COUNT / 256, 256>>>(ids, emb);
    // GRU layer 0
    gemm16_kernel<<<dim3(24, 2, 8), 256>>>(Wih0, nullptr, nullptr, O_X0, O_GI0,
                                           Whh0, nullptr, hidden, 0, O_GH0, 1024, 1024);
    gru_combine<<<128, 256>>>(O_GI0, O_GH0, bih0, bhh0, hidden, O_H0, 1024, O_SCAT, 2048, out_nh);
    // GRU layer 1
    gemm16_kernel<<<dim3(24, 2, 8), 256>>>(Wih1, nullptr, nullptr, O_H0, O_GI1,
                                           Whh1, nullptr, hidden + 32768, 0, O_GH1, 1024, 1024);
    gru_combine<<<128, 256>>>(O_GI1, O_GH1, bih1, bhh1, hidden + 32768,
                              O_XCAT, 3072, O_SCAT + 1024, 2048, out_nh + 32768);
    // state-part of both attention fc1 (+bias)
    gemm16_kernel<<<dim3(8, 2, 8), 256>>>(afc1w, afc1b, nullptr, O_SCAT, O_SV2,
                                          pfc1w, pfc1b, nullptr, O_SCAT, O_SV2 + 32768, 3072, 2048);
    big_att_f16<<<dim3(8, 128, 2), 256>>>(enc, encp, afc1w, pfc1w, afc2w, pfc2w);
    softmax_kernel<<<dim3(32, 2), 512>>>();
    ctx_kernel<<<dim3(32, 2, 8), 256>>>(enc, encp);
    // attn_fc on [h1, ctx, ctx_p]
    gemm16_kernel<<<dim3(8, 1, 8), 256>>>(nfcw, nfcb, nullptr, O_XCAT, O_FC,
                                          nfcw, nfcb, nullptr, O_XCAT, O_FC, 3072, 3072);
    relu_tr_kernel<<<128, 256>>>();
    logits_f16<<<250, 256>>>(fcw, fcb, out);
}